// round 1
// baseline (speedup 1.0000x reference)
#include <cuda_runtime.h>
#include <cuda_bf16.h>

// E8 lattice quantizer: for each row of 8 floats,
//   y1 = D8_quantize(x), y2 = D8_quantize(x - 0.5) + 0.5
//   out = (||x-y2|| < ||x-y1||) ? y2 : y1
//
// D8_quantize(x): f = rint(x); k = argmax|x-f| (first max);
//   g = f with g[k] += sign-ish fix toward x; use g if sum(g) even else f.
//
// Pure HBM-streaming: 32 B in + 32 B out per thread.

__device__ __forceinline__ float d8_quantize(const float x[8], float off, float y[8]) {
    float f[8], d[8];
    float sum = 0.0f;
    float maxabs = -1.0f;
    int k = 0;
#pragma unroll
    for (int i = 0; i < 8; i++) {
        float xi = x[i] - off;
        float fi = rintf(xi);      // round-half-to-even, matches jnp.round
        f[i] = fi;
        d[i] = xi - fi;
        sum += fi;
        float a = fabsf(d[i]);
        if (a > maxabs) { maxabs = a; k = i; }   // strict > keeps FIRST max (jnp.argmax)
    }
    float fix = (d[k] < 0.0f) ? -1.0f : 1.0f;    // dk==0 -> +1, matches where(dk<0,-1,1)
    // g = f except g[k] = f[k] + fix; sum(g) = sum + fix. Parity check:
    int sg = (int)(sum + fix);                   // exact: small integers in fp32
    bool g_even = ((sg & 1) == 0);               // (-3)&1==1 in two's complement: correct parity

    float dist = 0.0f;
#pragma unroll
    for (int i = 0; i < 8; i++) {
        float yi = f[i];
        if (g_even && (i == k)) yi += fix;
        yi += off;                                // shift back for the D8+1/2 coset
        y[i] = yi;
        float e = x[i] - yi;
        dist = fmaf(e, e, dist);
    }
    return dist;
}

__global__ void __launch_bounds__(256) e8_quantize_kernel(
    const float4* __restrict__ in4, float4* __restrict__ out4, int n_rows) {
    int t = blockIdx.x * blockDim.x + threadIdx.x;
    if (t >= n_rows) return;

    float4 v0 = in4[2 * t + 0];
    float4 v1 = in4[2 * t + 1];
    float x[8] = {v0.x, v0.y, v0.z, v0.w, v1.x, v1.y, v1.z, v1.w};

    float y1[8], y2[8];
    float s1 = d8_quantize(x, 0.0f, y1);
    float s2 = d8_quantize(x, 0.5f, y2);

    bool use2 = (s2 < s1);   // strict: ties -> y1, matching torch.argmin/jnp tie rule
    float4 o0, o1;
    o0.x = use2 ? y2[0] : y1[0];
    o0.y = use2 ? y2[1] : y1[1];
    o0.z = use2 ? y2[2] : y1[2];
    o0.w = use2 ? y2[3] : y1[3];
    o1.x = use2 ? y2[4] : y1[4];
    o1.y = use2 ? y2[5] : y1[5];
    o1.z = use2 ? y2[6] : y1[6];
    o1.w = use2 ? y2[7] : y1[7];

    out4[2 * t + 0] = o0;
    out4[2 * t + 1] = o1;
}

extern "C" void kernel_launch(void* const* d_in, const int* in_sizes, int n_in,
                              void* d_out, int out_size) {
    const float4* in4 = (const float4*)d_in[0];
    float4* out4 = (float4*)d_out;
    int n_rows = in_sizes[0] / 8;
    int threads = 256;
    int blocks = (n_rows + threads - 1) / threads;
    e8_quantize_kernel<<<blocks, threads>>>(in4, out4, n_rows);
}

// round 2
// speedup vs baseline: 1.0800x; 1.0800x over previous
#include <cuda_runtime.h>
#include <cuda_bf16.h>

// E8 lattice quantizer, ALU-minimized formulation.
//
// Per coset (off in {0, 0.5}):
//   f_i = rint(x_i - off); d_i = (x_i - off) - f_i
//   argmax chain tracks signed d_k (first max, strict >) and a one-hot bitmask.
//   fix = (d_k < 0) ? -1 : +1 ; g_even = ((int)sum(f) + (int)fix) & 1 == 0
//   chosen dist (closed form): s = g_even ? sumd2 + 1 - 2|d_k| : sumd2
//     [ dist(g) = sumd2 - d_k^2 + (d_k - fix)^2 = sumd2 + 1 - 2*fix*d_k,
//       and fix*d_k == |d_k| by construction ]
// Then pick coset by s2 < s1 (ties -> coset 1) and materialize output ONCE:
//   y_i = (use2 ? f2_i+0.5 : f1_i) + (onehot bit i ? (g_even ? fix : 0) : 0)

struct Coset {
    float s;    // distance^2 of chosen point to x'
    float add;  // g_even ? fix : 0
    int   oh;   // one-hot mask of argmax coordinate
};

__device__ __forceinline__ Coset d8_pass(const float x[8], float off, float fout[8]) {
    float dk, sumf, sumd2;
    int oh = 1;
    {
        float xi = x[0] - off;
        float fi = rintf(xi);          // round-half-to-even == jnp.round
        float di = xi - fi;
        fout[0] = fi + off;            // pre-shifted output candidate
        sumf  = fi;
        sumd2 = di * di;
        dk    = di;                    // chain starts at element 0 (first-max)
    }
#pragma unroll
    for (int i = 1; i < 8; i++) {
        float xi = x[i] - off;
        float fi = rintf(xi);
        float di = xi - fi;
        fout[i] = fi + off;
        sumf += fi;
        sumd2 = fmaf(di, di, sumd2);
        if (fabsf(di) > fabsf(dk)) { dk = di; oh = 1 << i; }  // strict >: first max
    }
    float fix = (dk < 0.0f) ? -1.0f : 1.0f;   // d_k == 0 -> +1, matches reference
    int sg = (int)sumf + (int)fix;            // exact small integers
    bool ge = ((sg & 1) == 0);                // two's complement: correct for negatives
    float m = fabsf(dk);
    Coset c;
    c.s   = ge ? fmaf(-2.0f, m, sumd2 + 1.0f) : sumd2;
    c.add = ge ? fix : 0.0f;
    c.oh  = oh;
    return c;
}

__global__ void __launch_bounds__(256) e8_quantize_kernel(
    const float4* __restrict__ in4, float4* __restrict__ out4, int n_rows) {
    int t = blockIdx.x * blockDim.x + threadIdx.x;
    if (t >= n_rows) return;

    float4 v0 = __ldcs(&in4[2 * t + 0]);   // streamed once: evict-first
    float4 v1 = __ldcs(&in4[2 * t + 1]);
    float x[8] = {v0.x, v0.y, v0.z, v0.w, v1.x, v1.y, v1.z, v1.w};

    float y1[8], y2[8];
    Coset c1 = d8_pass(x, 0.0f, y1);
    Coset c2 = d8_pass(x, 0.5f, y2);

    bool use2 = (c2.s < c1.s);              // strict: ties -> coset 1
    float add = use2 ? c2.add : c1.add;
    int   oh  = use2 ? c2.oh  : c1.oh;

    float y[8];
#pragma unroll
    for (int i = 0; i < 8; i++) {
        float fi = use2 ? y2[i] : y1[i];
        if (oh & (1 << i)) fi += add;       // LOP3-pred + predicated FADD
        y[i] = fi;
    }

    float4 o0, o1;
    o0.x = y[0]; o0.y = y[1]; o0.z = y[2]; o0.w = y[3];
    o1.x = y[4]; o1.y = y[5]; o1.z = y[6]; o1.w = y[7];
    __stcs(&out4[2 * t + 0], o0);
    __stcs(&out4[2 * t + 1], o1);
}

extern "C" void kernel_launch(void* const* d_in, const int* in_sizes, int n_in,
                              void* d_out, int out_size) {
    const float4* in4 = (const float4*)d_in[0];
    float4* out4 = (float4*)d_out;
    int n_rows = in_sizes[0] / 8;
    int threads = 256;
    int blocks = (n_rows + threads - 1) / threads;
    e8_quantize_kernel<<<blocks, threads>>>(in4, out4, n_rows);
}